// round 2
// baseline (speedup 1.0000x reference)
#include <cuda_runtime.h>
#include <math.h>

#define BBATCH 4
#define CC 64
#define HH 255
#define WW 256
#define FF 129
#define SP (FF*HH)       /* 32895 */
#define NVB 8            /* 2 variants * 4 batch */

// ---------------- scratch (device globals; no allocation allowed) ----------------
__device__ float g_Y1r[(size_t)BBATCH*CC*FF*WW];   // [b,c,f,g]
__device__ float g_Y1i[(size_t)BBATCH*CC*FF*WW];
__device__ float g_Z  [(size_t)NVB*128*SP];        // [vb,ch,(f,k)]
__device__ float g_Yc [(size_t)NVB*128*SP];        // conv out / normalized
__device__ float g_Vr [(size_t)NVB*CC*128*FF];     // [vb,c,h',f]
__device__ float g_Vi [(size_t)NVB*CC*128*FF];
__device__ float g_Mwc[WW*FF], g_Mws[WW*FF];       // forward W-DFT 256x129
__device__ float g_Mhc[HH*HH], g_Mhs[HH*HH];       // H-DFT 255x255 (symmetric)
__device__ float g_Mic[FF*WW], g_Mis[FF*WW];       // inverse W (Hermitian folded) 129x256
__device__ float g_mu[NVB*16], g_rs[NVB*16];

// ---------------- DFT matrix init (exact modular angle reduction, fp32 trig) ----------------
__global__ void init_mats() {
  int i = blockIdx.x * blockDim.x + threadIdx.x;
  const float TWO_PI = 6.2831853071795864769f;
  if (i < WW*FF) {
    int w = i / FF, f = i - w*FF;
    int t = (w*f) & (WW-1);
    float sn, cs; sincosf((float)t * (TWO_PI/WW), &sn, &cs);
    g_Mwc[i] = cs; g_Mws[i] = sn;
  }
  if (i < FF*WW) {
    int f = i / WW, w = i - f*WW;
    int t = (f*w) & (WW-1);
    float sn, cs; sincosf((float)t * (TWO_PI/WW), &sn, &cs);
    float amp = (f == 0 || f == FF-1) ? (1.0f/WW) : (2.0f/WW);
    g_Mic[i] = amp*cs; g_Mis[i] = amp*sn;
  }
  if (i < HH*HH) {
    int h = i / HH, k = i - h*HH;
    int t = (h*k) % HH;
    float sn, cs; sincosf((float)t * (TWO_PI/HH), &sn, &cs);
    g_Mhc[i] = cs; g_Mhs[i] = sn;
  }
}

// ---------------- unified complex-GEMM for all 5 stages ----------------
// Forward (E=+1): Cr = Ar@Bc + Ai@Bs ; Ci = Ai@Bc - Ar@Bs
// Inverse (E=-1): Cr = Ar@Bc - Ai@Bs ; Ci = Ai@Bc + Ar@Bs   (scale applied)
template<int STEP>
__global__ void __launch_bounds__(256) dft_gemm(const float* __restrict__ Aext,
                                                const float* __restrict__ bias,
                                                float* __restrict__ Cext)
{
  constexpr bool HAS_AI  = (STEP==2 || STEP==4 || STEP==5);
  constexpr bool WANT_CI = (STEP==1 || STEP==2 || STEP==4);
  constexpr bool HAS_BS  = (STEP!=3);
  constexpr float E = (STEP==4 || STEP==5) ? -1.0f : 1.0f;
  constexpr float SCALE = (STEP==4) ? (1.0f/(float)HH) : 1.0f;
  constexpr int M = (STEP==1) ? BBATCH*CC*WW :
                    (STEP==2 || STEP==4) ? NVB*CC*FF :
                    (STEP==3) ? NVB*128 : NVB*CC*128;
  constexpr int N = (STEP==1) ? FF : (STEP==2) ? HH : (STEP==3) ? SP :
                    (STEP==4) ? 128 : WW;
  constexpr int K = (STEP==1) ? WW : (STEP==2 || STEP==4) ? HH :
                    (STEP==3) ? 128 : FF;

  const float* Ar0; const float* Ai0 = nullptr;
  const float* Bc0; const float* Bs0 = nullptr;
  float* Cr0; float* Ci0 = nullptr;
  if constexpr (STEP==1) { Ar0=Aext; Bc0=g_Mwc; Bs0=g_Mws; Cr0=g_Y1r; Ci0=g_Y1i; }
  else if constexpr (STEP==2) { Ar0=g_Y1r; Ai0=g_Y1i; Bc0=g_Mhc; Bs0=g_Mhs;
                                Cr0=g_Z; Ci0=g_Z + (size_t)64*SP; }
  else if constexpr (STEP==3) { Ar0=Aext; Bc0=g_Z; Cr0=g_Yc; }
  else if constexpr (STEP==4) { Ar0=g_Yc; Ai0=g_Yc + (size_t)64*SP; Bc0=g_Mhc; Bs0=g_Mhs;
                                Cr0=g_Vr; Ci0=g_Vi; }
  else                        { Ar0=g_Vr; Ai0=g_Vi; Bc0=g_Mic; Bs0=g_Mis; Cr0=Cext; }

  __shared__ __align__(16) float sAr[16][64];
  __shared__ __align__(16) float sAi[HAS_AI ? 16 : 1][64];
  __shared__ __align__(16) float sBc[16][64];
  __shared__ __align__(16) float sBs[HAS_BS ? 16 : 1][64];

  const int tid = threadIdx.x;
  const int m0 = blockIdx.y * 64, n0 = blockIdx.x * 64;

  // --- per-thread A-tile load coords: 4 consecutive k for one row ---
  const int lr = tid >> 2;            // row within tile
  const int lk = (tid & 3) * 4;       // k quad
  const int mA = m0 + lr;
  const bool mvalid = (mA < M);
  long a_off = 0;
  if constexpr (STEP==1) a_off = (long)mA * WW;
  else if constexpr (STEP==2) {
    int f = mA % FF; int t2 = mA / FF; int c = t2 % CC; int vb = t2 / CC;
    a_off = ((long)((vb & 3)*CC + c)*FF + f)*WW + (vb >> 2);
  } else if constexpr (STEP==3) a_off = (long)(mA & 127) * 128;
  else if constexpr (STEP==4) {
    int f = mA % FF; int t2 = mA / FF; int c = t2 % CC; int vb = t2 / CC;
    a_off = (long)(vb*128 + c)*SP + (long)f*HH;
  } else a_off = (long)mA * FF;

  // --- per-thread B-tile load coords ---
  const int kb = tid >> 4;
  const int nq = (tid & 15) * 4;
  int ldb; long b_base = 0; int bcol = 0;
  if constexpr (STEP==1) ldb = FF;
  else if constexpr (STEP==2) ldb = HH;
  else if constexpr (STEP==3) { ldb = SP; b_base = (long)(m0 >> 7) * 128 * SP; }
  else if constexpr (STEP==4) { ldb = HH; bcol = (((m0 / FF) / CC) >> 2) * 127; }
  else ldb = WW;

  float cr[4][4] = {};
  float ci[4][4] = {};
  const int ty4 = (tid >> 4) * 4;
  const int tx4 = (tid & 15) * 4;

  // register staging for software pipeline (prefetch next k-tile during compute)
  float rAr[4], rAi[4], rBc[4], rBs[4];

  // ---- prologue: stage k-tile 0 ----
  {
    #pragma unroll
    for (int j = 0; j < 4; j++) {
      int kk = lk + j;
      float vr = 0.f, vi = 0.f;
      if (mvalid && kk < K) {
        vr = Ar0[a_off + kk];
        if constexpr (HAS_AI) vi = Ai0[a_off + kk];
      }
      rAr[j] = vr;
      if constexpr (HAS_AI) rAi[j] = vi;
    }
    int kk = kb;
    #pragma unroll
    for (int j = 0; j < 4; j++) {
      int n = n0 + nq + j;
      float vc = 0.f, vs = 0.f;
      if (kk < K && n < N) {
        long bo = b_base + (long)kk * ldb + n + bcol;
        vc = Bc0[bo];
        if constexpr (HAS_BS) vs = Bs0[bo];
      }
      rBc[j] = vc;
      if constexpr (HAS_BS) rBs[j] = vs;
    }
  }

  for (int k0 = 0; k0 < K; k0 += 16) {
    // ---- commit staged tile to smem ----
    #pragma unroll
    for (int j = 0; j < 4; j++) {
      sAr[lk + j][lr] = rAr[j];
      if constexpr (HAS_AI) sAi[lk + j][lr] = rAi[j];
    }
    #pragma unroll
    for (int j = 0; j < 4; j++) {
      sBc[kb][nq + j] = rBc[j];
      if constexpr (HAS_BS) sBs[kb][nq + j] = rBs[j];
    }
    __syncthreads();

    // ---- prefetch next tile into registers (latency hidden by compute below) ----
    if (k0 + 16 < K) {
      #pragma unroll
      for (int j = 0; j < 4; j++) {
        int kk = k0 + 16 + lk + j;
        float vr = 0.f, vi = 0.f;
        if (mvalid && kk < K) {
          vr = Ar0[a_off + kk];
          if constexpr (HAS_AI) vi = Ai0[a_off + kk];
        }
        rAr[j] = vr;
        if constexpr (HAS_AI) rAi[j] = vi;
      }
      int kk = k0 + 16 + kb;
      #pragma unroll
      for (int j = 0; j < 4; j++) {
        int n = n0 + nq + j;
        float vc = 0.f, vs = 0.f;
        if (kk < K && n < N) {
          long bo = b_base + (long)kk * ldb + n + bcol;
          vc = Bc0[bo];
          if constexpr (HAS_BS) vs = Bs0[bo];
        }
        rBc[j] = vc;
        if constexpr (HAS_BS) rBs[j] = vs;
      }
    }

    // ---- compute 16 k-steps from smem ----
    #pragma unroll
    for (int kk = 0; kk < 16; kk++) {
      float ar[4], ai[4], bc[4], bs[4];
      *(float4*)ar = *(const float4*)&sAr[kk][ty4];
      *(float4*)bc = *(const float4*)&sBc[kk][tx4];
      if constexpr (HAS_AI) *(float4*)ai = *(const float4*)&sAi[kk][ty4];
      if constexpr (HAS_BS) *(float4*)bs = *(const float4*)&sBs[kk][tx4];
      #pragma unroll
      for (int i = 0; i < 4; i++)
        #pragma unroll
        for (int j = 0; j < 4; j++) {
          cr[i][j] += ar[i]*bc[j];
          if constexpr (HAS_AI) cr[i][j] += E*(ai[i]*bs[j]);
          if constexpr (WANT_CI) {
            if constexpr (HAS_AI) ci[i][j] += ai[i]*bc[j];
            ci[i][j] -= E*(ar[i]*bs[j]);
          }
        }
    }
    __syncthreads();
  }

  #pragma unroll
  for (int i = 0; i < 4; i++) {
    int m = m0 + ty4 + i;
    if (m >= M) continue;
    #pragma unroll
    for (int j = 0; j < 4; j++) {
      int n = n0 + tx4 + j;
      if (n >= N) continue;
      long co;
      if constexpr (STEP==1) co = ((long)(m >> 8)*FF + n)*WW + (m & 255);
      else if constexpr (STEP==2) {
        int f = m % FF; int t2 = m / FF; int c = t2 % CC; int vb = t2 / CC;
        co = (long)vb*128*SP + (long)c*SP + (long)f*HH + n;
      } else if constexpr (STEP==3) co = (long)(m >> 7)*128*SP + (long)(m & 127)*SP + n;
      else if constexpr (STEP==4) co = ((long)(m / FF)*128 + n)*FF + (m % FF);
      else {
        int hq = m & 127; int t2 = m >> 7; int c = t2 % CC; int vb = t2 / CC;
        co = ((long)((vb & 3)*CC + c)*WW + (hq + (vb >> 2)*128))*WW + n;
      }
      float v = cr[i][j] * SCALE;
      if constexpr (STEP==3) v += bias[m & 127];
      Cr0[co] = v;
      if constexpr (WANT_CI) Ci0[co] = ci[i][j] * SCALE;
    }
  }
}

// ---------------- GroupNorm ----------------
__global__ void __launch_bounds__(1024) gn_stats() {
  const int tid = threadIdx.x;
  const long base = (long)blockIdx.x * 8 * SP;   // blockIdx = vb*16 + group
  const int LEN = 8 * SP;
  double s = 0.0, q = 0.0;
  for (int i = tid; i < LEN; i += 1024) {
    float v = g_Yc[base + i];
    s += (double)v; q += (double)v * (double)v;
  }
  for (int o = 16; o; o >>= 1) {
    s += __shfl_down_sync(0xffffffffu, s, o);
    q += __shfl_down_sync(0xffffffffu, q, o);
  }
  __shared__ double ss[32], sq[32];
  if ((tid & 31) == 0) { ss[tid >> 5] = s; sq[tid >> 5] = q; }
  __syncthreads();
  if (tid == 0) {
    double S = 0.0, Q = 0.0;
    for (int w = 0; w < 32; w++) { S += ss[w]; Q += sq[w]; }
    double nrm = (double)LEN;
    double mu = S / nrm;
    double var = Q / nrm - mu * mu;
    g_mu[blockIdx.x] = (float)mu;
    g_rs[blockIdx.x] = (float)(1.0 / sqrt(var + 1e-5));
  }
}

__global__ void __launch_bounds__(256) gn_norm(const float* __restrict__ gamma,
                                               const float* __restrict__ beta) {
  long i = (long)blockIdx.x * 256 + threadIdx.x;
  if (i >= (long)NVB * 128 * SP) return;
  int ch = (int)((i / SP) & 127);
  int sidx = (int)(i / ((long)8 * SP));
  float v = (g_Yc[i] - g_mu[sidx]) * g_rs[sidx] * gamma[ch] + beta[ch];
  g_Yc[i] = fmaxf(v, 0.f);
}

// ---------------- launch ----------------
extern "C" void kernel_launch(void* const* d_in, const int* in_sizes, int n_in,
                              void* d_out, int out_size) {
  const float* x      = (const float*)d_in[0];
  const float* conv_w = (const float*)d_in[1];
  const float* conv_b = (const float*)d_in[2];
  const float* gamma  = (const float*)d_in[3];
  const float* beta   = (const float*)d_in[4];
  float* out = (float*)d_out;

  init_mats<<<(HH*HH + 255) / 256, 256>>>();

  // 1: rFFT-W   M=65536 N=129 K=256   (shared between bot/top)
  dft_gemm<1><<<dim3((FF + 63) / 64, (BBATCH*CC*WW) / 64), 256>>>(x, nullptr, nullptr);
  // 2: forward DFT-H   M=66048 N=255 K=255
  dft_gemm<2><<<dim3((HH + 63) / 64, (NVB*CC*FF) / 64), 256>>>(nullptr, nullptr, nullptr);
  // 3: 1x1 conv   M=1024 N=32895 K=128 (+bias)
  dft_gemm<3><<<dim3((SP + 63) / 64, (NVB*128) / 64), 256>>>(conv_w, conv_b, nullptr);
  // GroupNorm + ReLU
  gn_stats<<<NVB*16, 1024>>>();
  gn_norm<<<(int)(((long)NVB*128*SP) / 256), 256>>>(gamma, beta);
  // 4: inverse DFT-H (only needed 128 rows; top offset 127)   M=66048 N=128 K=255
  dft_gemm<4><<<dim3(2, (NVB*CC*FF) / 64), 256>>>(nullptr, nullptr, nullptr);
  // 5: irFFT-W direct to output   M=65536 N=256 K=129
  dft_gemm<5><<<dim3(WW / 64, (NVB*CC*128) / 64), 256>>>(nullptr, nullptr, out);
}